// round 6
// baseline (speedup 1.0000x reference)
#include <cuda_runtime.h>
#include <cstdint>

#define CIN   32
#define COUT  64
#define KVOL  4
#define KSTRIDE (CIN * COUT + 8)   // 2056 floats (even -> ull-aligned rows)
#define EPS   1e-4f
#define LEAK  0.333f

#define CONV_BLOCKS  888           // 148 SMs * 6 blocks (smem-limited) = 1 wave
#define STATS_BLOCKS 1184          // 148 SMs * 8

__device__ float g_partials[STATS_BLOCKS * 128];  // [block][0:64 sum, 64:128 sumsq]
__device__ float g_coef[128];                     // [0:64 A, 64:128 B]

// ---- packed f32x2 helpers (sm_103a) ---------------------------------------
__device__ __forceinline__ unsigned long long pack2(float x) {
    unsigned long long r;
    asm("mov.b64 %0, {%1, %1};" : "=l"(r) : "f"(x));
    return r;
}
__device__ __forceinline__ unsigned long long ffma2(unsigned long long a,
                                                    unsigned long long b,
                                                    unsigned long long c) {
    unsigned long long d;
    asm("fma.rn.f32x2 %0, %1, %2, %3;" : "=l"(d) : "l"(a), "l"(b), "l"(c));
    return d;
}
__device__ __forceinline__ void unpack2(unsigned long long v, float& lo, float& hi) {
    asm("mov.b64 {%0, %1}, %2;" : "=f"(lo), "=f"(hi) : "l"(v));
}

// ---- dummy (shifts ncu capture slot so conv gets profiled) -----------------
__global__ void dummy_k() {}

// ---- kernel 1: warp-per-row channel-parallel conv --------------------------
// lane l owns channels {2l, 2l+1}. Per row: 1 coalesced feat LDG.32 (1 line),
// 32 shfl broadcasts, 32 broadcast LDS.64 weight reads, 32 FFMA2, 1 RED.64
// (warp writes 256B contiguous -> 2 lines, vs 32 scattered lines before).
__global__ __launch_bounds__(256, 4) void conv_scatter(
    const float* __restrict__ feat,
    const float* __restrict__ weight,
    const int*   __restrict__ out_idx,
    const int*   __restrict__ kern_idx,
    float*       __restrict__ out,
    int n_rows)
{
    __shared__ float wsh[KVOL * KSTRIDE];
    for (int t = threadIdx.x; t < KVOL * CIN * COUT; t += blockDim.x) {
        int k = t >> 11;          // / 2048
        int r = t & 2047;
        wsh[k * KSTRIDE + r] = weight[t];
    }
    __syncthreads();

    int lane   = threadIdx.x & 31;
    int gwarp  = (blockIdx.x * blockDim.x + threadIdx.x) >> 5;
    int nwarps = (gridDim.x * blockDim.x) >> 5;
    const unsigned long long* wbase =
        reinterpret_cast<const unsigned long long*>(wsh);

    for (int row = gwarp; row < n_rows; row += nwarps) {
        int k = kern_idx[row];          // uniform broadcast load
        int o = out_idx[row];
        float f = feat[(size_t)row * CIN + lane];   // coalesced: 1 line/warp

        const unsigned long long* wk = wbase + (size_t)k * (KSTRIDE / 2) + lane;

        unsigned long long acc = 0ull;
        #pragma unroll
        for (int j = 0; j < CIN; j++) {
            float fj = __shfl_sync(0xFFFFFFFFu, f, j);
            unsigned long long w = wk[j * (COUT / 2)];   // channels 2l,2l+1 of row j
            acc = ffma2(w, pack2(fj), acc);
        }

        float lo, hi;
        unpack2(acc, lo, hi);
        atomicAdd(reinterpret_cast<float2*>(out + (size_t)o * COUT + 2 * lane),
                  make_float2(lo, hi));   // warp: 256B contiguous RED.64
    }
}

// ---- kernel 2: per-channel sum / sumsq partials ----------------------------
__global__ __launch_bounds__(256) void stats_kernel(const float* __restrict__ out,
                                                    int n_out)
{
    __shared__ float sh[128];
    if (threadIdx.x < 128) sh[threadIdx.x] = 0.f;
    __syncthreads();

    int gid = blockIdx.x * blockDim.x + threadIdx.x;
    int c4 = threadIdx.x & 15;                 // fixed float4-column per thread
    int row0 = gid >> 4;
    int rstride = (gridDim.x * blockDim.x) >> 4;
    const float4* o4 = reinterpret_cast<const float4*>(out);

    float4 s = make_float4(0.f, 0.f, 0.f, 0.f);
    float4 q = make_float4(0.f, 0.f, 0.f, 0.f);
    for (int r = row0; r < n_out; r += rstride) {
        float4 v = o4[(size_t)r * 16 + c4];
        s.x += v.x; s.y += v.y; s.z += v.z; s.w += v.w;
        q.x += v.x * v.x; q.y += v.y * v.y; q.z += v.z * v.z; q.w += v.w * v.w;
    }
    s.x += __shfl_down_sync(0xFFFFFFFFu, s.x, 16);
    s.y += __shfl_down_sync(0xFFFFFFFFu, s.y, 16);
    s.z += __shfl_down_sync(0xFFFFFFFFu, s.z, 16);
    s.w += __shfl_down_sync(0xFFFFFFFFu, s.w, 16);
    q.x += __shfl_down_sync(0xFFFFFFFFu, q.x, 16);
    q.y += __shfl_down_sync(0xFFFFFFFFu, q.y, 16);
    q.z += __shfl_down_sync(0xFFFFFFFFu, q.z, 16);
    q.w += __shfl_down_sync(0xFFFFFFFFu, q.w, 16);

    if ((threadIdx.x & 31) < 16) {
        atomicAdd(&sh[c4 * 4 + 0], s.x);
        atomicAdd(&sh[c4 * 4 + 1], s.y);
        atomicAdd(&sh[c4 * 4 + 2], s.z);
        atomicAdd(&sh[c4 * 4 + 3], s.w);
        atomicAdd(&sh[64 + c4 * 4 + 0], q.x);
        atomicAdd(&sh[64 + c4 * 4 + 1], q.y);
        atomicAdd(&sh[64 + c4 * 4 + 2], q.z);
        atomicAdd(&sh[64 + c4 * 4 + 3], q.w);
    }
    __syncthreads();
    if (threadIdx.x < 128)
        g_partials[blockIdx.x * 128 + threadIdx.x] = sh[threadIdx.x];
}

// ---- kernel 3: reduce partials -> per-channel A,B coefficients -------------
__global__ void coef_kernel(const float* __restrict__ gamma,
                            const float* __restrict__ beta,
                            int n_out)
{
    int t = threadIdx.x;   // 0..127
    float acc = 0.f;
    #pragma unroll 8
    for (int b = 0; b < STATS_BLOCKS; b++)
        acc += g_partials[b * 128 + t];
    __shared__ float tot[128];
    tot[t] = acc;
    __syncthreads();
    if (t < 64) {
        float inv_n = 1.0f / (float)n_out;
        float mean = tot[t] * inv_n;
        float var  = tot[64 + t] * inv_n - mean * mean;
        float A = gamma[t] * rsqrtf(var + EPS);
        float B = beta[t] - mean * A;
        g_coef[t] = A;
        g_coef[64 + t] = B;
    }
}

// ---- kernel 4: normalize + leaky relu (in place) ---------------------------
__global__ __launch_bounds__(256) void norm_kernel(float* __restrict__ out, int n_out)
{
    int gid = blockIdx.x * blockDim.x + threadIdx.x;
    int c4 = threadIdx.x & 15;
    const float4* cf = reinterpret_cast<const float4*>(g_coef);
    float4 A = cf[c4];
    float4 B = cf[16 + c4];
    int row0 = gid >> 4;
    int rstride = (gridDim.x * blockDim.x) >> 4;
    float4* o4 = reinterpret_cast<float4*>(out);
    for (int r = row0; r < n_out; r += rstride) {
        size_t idx = (size_t)r * 16 + c4;
        float4 v = o4[idx];
        float4 y;
        y.x = fmaf(v.x, A.x, B.x);
        y.y = fmaf(v.y, A.y, B.y);
        y.z = fmaf(v.z, A.z, B.z);
        y.w = fmaf(v.w, A.w, B.w);
        y.x = fmaxf(y.x, LEAK * y.x);
        y.y = fmaxf(y.y, LEAK * y.y);
        y.z = fmaxf(y.z, LEAK * y.z);
        y.w = fmaxf(y.w, LEAK * y.w);
        o4[idx] = y;
    }
}

// ---- launch ----------------------------------------------------------------
extern "C" void kernel_launch(void* const* d_in, const int* in_sizes, int n_in,
                              void* d_out, int out_size)
{
    const float* feat    = (const float*)d_in[0];
    const float* weight  = (const float*)d_in[1];
    // d_in[2] = bias: cancelled exactly by BN mean subtraction
    const float* gamma   = (const float*)d_in[3];
    const float* beta    = (const float*)d_in[4];
    const int*   out_idx = (const int*)d_in[5];
    const int*   kern_idx= (const int*)d_in[6];
    int n_rows = in_sizes[0] / CIN;
    int n_out  = out_size / COUT;
    float* out = (float*)d_out;

    cudaMemsetAsync(d_out, 0, (size_t)out_size * sizeof(float));
    // dummies: shift ncu's fixed capture slot (-s 5 -c 1) toward conv_scatter
    dummy_k<<<1, 32>>>();
    dummy_k<<<1, 32>>>();
    dummy_k<<<1, 32>>>();
    conv_scatter<<<CONV_BLOCKS, 256>>>(feat, weight, out_idx, kern_idx, out, n_rows);
    stats_kernel<<<STATS_BLOCKS, 256>>>(out, n_out);
    coef_kernel<<<1, 128>>>(gamma, beta, n_out);
    norm_kernel<<<1184, 256>>>(out, n_out);
}